// round 5
// baseline (speedup 1.0000x reference)
#include <cuda_runtime.h>
#include <cuda_bf16.h>
#include <stdint.h>

#define KTOT 1024
#define DIM  64
#define HW   4096
#define QELEMS 4194304
#define DELTA 2.5e-3f
#define CAP  16
#define INF __int_as_float(0x7f800000)

// dynamic smem offsets (bytes)
#define XS_OFF 0        // f32 xs[64][128]                    32768
#define B_OFF  32768    // bf16 B[256][72] padded             36864
#define CN_OFF 69632    // f32 cn[256]                         1024
#define CD_OFF 70656    // u16 cd[128 row][8 slot][CAP]       32768
#define CT_OFF 103424   // u16 cnt[128][8]                     2048
#define XN_OFF 105472   // f32 xn[128]                          512
#define SI_OFF 105984   // i32 sidx[128]                        512
#define LR_OFF 106496   // f32 lred[256]                       1024
#define SMEM_BYTES 107520

__device__ float g_cnorm[KTOT];
__device__ __align__(16) __nv_bfloat16 g_cbb[KTOT*DIM];

// prep: bf16 codebook copy, ||c||^2 (per-product rounding, ascending d), zero loss
__global__ void vq_prep(const float* __restrict__ cb, float* __restrict__ loss_ptr){
    int k = blockIdx.x*256 + threadIdx.x;
    if (k==0) *loss_ptr = 0.0f;
    if (k < KTOT){
        float s = 0.0f;
        #pragma unroll
        for (int d=0; d<DIM; ++d){
            float c = cb[k*DIM+d];
            g_cbb[k*DIM+d] = __float2bfloat16(c);
            s = __fadd_rn(s, __fmul_rn(c,c));
        }
        g_cnorm[k] = s;
    }
}

__device__ __forceinline__ uint32_t packbf(float lo, float hi){
    __nv_bfloat162 h = __floats2bfloat162_rn(lo, hi);   // .x = lo (low half)
    return *(uint32_t*)&h;
}

__global__ void __launch_bounds__(256,2) vq_hmma_kernel(
    const float* __restrict__ x, const float* __restrict__ cb,
    float* __restrict__ out, float* __restrict__ loss_ptr)
{
    extern __shared__ char smc[];
    float*          xs  = (float*)(smc + XS_OFF);
    __nv_bfloat16*  Bs  = (__nv_bfloat16*)(smc + B_OFF);
    float*          cns = (float*)(smc + CN_OFF);
    uint16_t*       cd  = (uint16_t*)(smc + CD_OFF);
    uint16_t*       cta = (uint16_t*)(smc + CT_OFF);
    float*          xns = (float*)(smc + XN_OFF);
    int*            sid = (int*)(smc + SI_OFF);
    float*          lrd = (float*)(smc + LR_OFF);

    const int tid = threadIdx.x;
    const int b = blockIdx.x>>5, h0 = (blockIdx.x&31)*2;

    // ---- load x tile [d][m] (coalesced over w) ----
    {
        int w=tid&63, hh=(tid>>6)&1, dh=(tid>>7)*32, m=hh*64+w;
        const float* xb = x + (size_t)b*DIM*HW + (size_t)(h0+hh)*64 + w;
        #pragma unroll
        for (int i=0;i<32;i++){ int d=dh+i; xs[d*128+m] = xb[(size_t)d*HW]; }
    }
    __syncthreads();

    // ---- per-row ||x||^2 (mul/add, ascending d) ----
    if (tid<128){
        float s=0.0f;
        #pragma unroll
        for (int d=0; d<DIM; ++d){ float v=xs[d*128+tid]; s=__fadd_rn(s,__fmul_rn(v,v)); }
        xns[tid]=s;
    }

    const int lane = tid&31, w = tid>>5;
    const int g = lane>>2, tg = lane&3;
    const int mbase = (w&3)*32, nhalf = w>>2, slot = nhalf*4 + tg;
    const int R[4] = { mbase+g, mbase+8+g, mbase+16+g, mbase+24+g };

    // ---- A fragments once (m16n8k16 row-major layout, built from fp32 xs) ----
    uint32_t afr[2][4][4];
    #pragma unroll
    for (int mt=0; mt<2; ++mt)
        #pragma unroll
        for (int ks=0; ks<4; ++ks){
            int R0 = mbase + mt*16 + g, R1 = R0 + 8;
            int c0 = ks*16 + 2*tg, c2 = c0 + 8;
            afr[mt][ks][0] = packbf(xs[c0*128+R0], xs[(c0+1)*128+R0]);
            afr[mt][ks][1] = packbf(xs[c0*128+R1], xs[(c0+1)*128+R1]);
            afr[mt][ks][2] = packbf(xs[c2*128+R0], xs[(c2+1)*128+R0]);
            afr[mt][ks][3] = packbf(xs[c2*128+R1], xs[(c2+1)*128+R1]);
        }

    float runmin[4] = {INF,INF,INF,INF};
    int   cnt[4]    = {0,0,0,0};

    for (int ch=0; ch<4; ++ch){
        // ---- load B chunk (256 rows x 64 bf16 = 2048 uint4) + cn chunk ----
        {
            const uint4* src = ((const uint4*)g_cbb) + ch*2048;   // FIX: was ch*1024
            #pragma unroll
            for (int j=tid; j<2048; j+=256){
                int row=j>>3, part=j&7;
                *(uint4*)(Bs + row*72 + part*8) = src[j];
            }
            cns[tid] = g_cnorm[ch*256+tid];
        }
        __syncthreads();

        #pragma unroll 1
        for (int nt=0; nt<16; ++nt){
            int n0 = nhalf*128 + nt*8;
            float acc[2][4] = {{0,0,0,0},{0,0,0,0}};
            #pragma unroll
            for (int ks=0; ks<4; ++ks){
                uint32_t b0 = *(const uint32_t*)(Bs + (n0+g)*72 + ks*16 + 2*tg);
                uint32_t b1 = *(const uint32_t*)(Bs + (n0+g)*72 + ks*16 + 2*tg + 8);
                #pragma unroll
                for (int mt=0; mt<2; ++mt){
                    asm volatile(
                        "mma.sync.aligned.m16n8k16.row.col.f32.bf16.bf16.f32 "
                        "{%0,%1,%2,%3}, {%4,%5,%6,%7}, {%8,%9}, {%0,%1,%2,%3};"
                        : "+f"(acc[mt][0]),"+f"(acc[mt][1]),"+f"(acc[mt][2]),"+f"(acc[mt][3])
                        : "r"(afr[mt][ks][0]),"r"(afr[mt][ks][1]),"r"(afr[mt][ks][2]),"r"(afr[mt][ks][3]),
                          "r"(b0),"r"(b1));
                }
            }
            // scores + candidate window
            #pragma unroll
            for (int mt=0; mt<2; ++mt)
                #pragma unroll
                for (int j=0; j<4; ++j){
                    int lr = mt*2 + (j>>1);
                    int nc = n0 + 2*tg + (j&1);
                    float s = fmaf(-2.0f, acc[mt][j], cns[nc]);
                    if (s < runmin[lr] + DELTA){
                        if (cnt[lr] < CAP) cd[R[lr]*128 + slot*CAP + cnt[lr]] = (uint16_t)(ch*256 + nc);
                        cnt[lr]++;
                    }
                    if (s < runmin[lr]) runmin[lr] = s;
                }
            // share running min across the 4 lanes of each quad (same rows)
            #pragma unroll
            for (int lr=0; lr<4; ++lr){
                float v = runmin[lr];
                v = fminf(v, __shfl_xor_sync(0xffffffffu, v, 1));
                v = fminf(v, __shfl_xor_sync(0xffffffffu, v, 2));
                runmin[lr] = v;
            }
        }
        __syncthreads();   // B consumed before next chunk overwrite
    }

    #pragma unroll
    for (int lr=0; lr<4; ++lr) cta[R[lr]*8 + slot] = (uint16_t)cnt[lr];
    __syncthreads();

    // ---- exact rescore (R1 numerics): gather candidates, sort ascending k ----
    if (tid<128){
        uint16_t list[128];
        int tot = 0; bool ovf = false;
        #pragma unroll
        for (int s2=0; s2<8; ++s2){
            int c = cta[tid*8+s2];
            if (c > CAP){ ovf = true; }
            else for (int i=0; i<c; ++i) list[tot++] = cd[tid*128 + s2*CAP + i];
        }
        float xnv = xns[tid];
        float best = INF; int bk = 0;
        if (!ovf){
            for (int i=1; i<tot; ++i){           // insertion sort ascending
                uint16_t v = list[i]; int j = i-1;
                while (j>=0 && list[j]>v){ list[j+1]=list[j]; --j; }
                list[j+1]=v;
            }
            for (int i=0; i<tot; ++i){
                int k = list[i];
                const float* cr = cb + k*DIM;
                float dot = 0.0f;
                #pragma unroll
                for (int d=0; d<DIM; ++d) dot = fmaf(xs[d*128+tid], __ldg(cr+d), dot);
                float sc = __fsub_rn(__fadd_rn(xnv, g_cnorm[k]), __fmul_rn(2.0f, dot));
                if (sc < best){ best = sc; bk = k; }
            }
        } else {
            for (int k=0; k<KTOT; ++k){
                const float* cr = cb + k*DIM;
                float dot = 0.0f;
                #pragma unroll
                for (int d=0; d<DIM; ++d) dot = fmaf(xs[d*128+tid], __ldg(cr+d), dot);
                float sc = __fsub_rn(__fadd_rn(xnv, g_cnorm[k]), __fmul_rn(2.0f, dot));
                if (sc < best){ best = sc; bk = k; }
            }
        }
        sid[tid] = bk;
    }
    __syncthreads();

    // ---- straight-through output + loss (R1 elementwise rounding) ----
    float lsum = 0.0f;
    {
        int w2=tid&63, hh=(tid>>6)&1, dh=(tid>>7)*32, m=hh*64+w2;
        int k = sid[m];
        const float* cr = cb + k*DIM;
        float* ob = out + (size_t)b*DIM*HW + (size_t)(h0+hh)*64 + w2;
        #pragma unroll
        for (int i=0;i<32;i++){
            int d=dh+i;
            float q = __ldg(cr+d), xv = xs[d*128+m];
            float df = __fsub_rn(q, xv);
            lsum = __fadd_rn(lsum, __fmul_rn(df, df));
            ob[(size_t)d*HW] = __fadd_rn(xv, df);
        }
    }
    lrd[tid] = lsum;
    __syncthreads();
    #pragma unroll
    for (int s2=128; s2>0; s2>>=1){
        if (tid<s2) lrd[tid] = __fadd_rn(lrd[tid], lrd[tid+s2]);
        __syncthreads();
    }
    if (tid==0) atomicAdd(loss_ptr, lrd[0] * (1.25f/(float)QELEMS));
}

extern "C" void kernel_launch(void* const* d_in, const int* in_sizes, int n_in,
                              void* d_out, int out_size) {
    const float* x  = (const float*)d_in[0];
    const float* cb = (const float*)d_in[1];
    float* out = (float*)d_out;
    float* loss_ptr = out + (out_size - 1);

    cudaFuncSetAttribute(vq_hmma_kernel, cudaFuncAttributeMaxDynamicSharedMemorySize, SMEM_BYTES);
    vq_prep<<<4, 256>>>(cb, loss_ptr);
    vq_hmma_kernel<<<512, 256, SMEM_BYTES>>>(x, cb, out, loss_ptr);
}